// round 5
// baseline (speedup 1.0000x reference)
#include <cuda_runtime.h>

#define NSTAGES 12
#define NPAIRS  2048
#define NCOLS   4096
#define NROWS   4096
#define RPC     4       // rows per CTA -> 64 KB smem -> 2 CTAs/SM
#define TPB     512

// Bank-conflict-free swizzle for the remaining exchange patterns (D = 8, 64, 512).
__device__ __forceinline__ int swz(int a) {
    return a ^ ((a >> 5) & 7) ^ (((a >> 6) & 3) << 3);
}

// Polynomial sin/cos for |a| <~ 0.15 (angles are 0.02*N(0,1)).
// Returns c1 = cos(a)-1 (no cancellation) and s = sin(a). All FMA-pipe.
__device__ __forceinline__ float2 cs_poly(float a) {
    float x2 = a * a;
    float c1 = x2 * fmaf(x2, (1.0f / 24.0f), -0.5f);
    float s  = a * fmaf(x2, fmaf(x2, (1.0f / 120.0f), (-1.0f / 6.0f)), 1.0f);
    return make_float2(c1, s);
}

// Rotation using c1 = c-1: 4 FFMA, = (c*v0 - s*v1, s*v0 + c*v1).
__device__ __forceinline__ void rot(float2 cs, float& a, float& b) {
    float ta = fmaf(cs.x, a, a);
    float tb = fmaf(cs.x, b, b);
    float y0 = fmaf(-cs.y, b, ta);
    float y1 = fmaf(cs.y, a, tb);
    a = y0;
    b = y1;
}

// Three butterfly stages (dist D, 2D, 4D) on 8 register-resident values.
__device__ __forceinline__ void rot3(const float2 cs[3][4], float v[8]) {
#pragma unroll
    for (int m = 0; m < 4; m++) rot(cs[0][m], v[2 * m], v[2 * m + 1]);
#pragma unroll
    for (int m = 0; m < 4; m++) {
        int j = ((m >> 1) << 2) | (m & 1);
        rot(cs[1][m], v[j], v[j + 2]);
    }
#pragma unroll
    for (int m = 0; m < 4; m++) rot(cs[2][m], v[m], v[m + 4]);
}

// 8x8 register transpose within each 8-lane group: after this,
// new v[j] on lane l == old v[l&7] on lane (l&24)|j.
// XOR block-swap: 3 rounds (m=1,2,4), 4 shfl_xor per round, static reg indices.
__device__ __forceinline__ void transpose8(float v[8], unsigned l) {
#pragma unroll
    for (int m = 1; m <= 4; m <<= 1) {
        bool hi = (l & m) != 0;
#pragma unroll
        for (int j = 0; j < 8; j++) {
            if ((j & m) == 0) {
                int jp = j | m;
                float send = hi ? v[j] : v[jp];
                float recv = __shfl_xor_sync(0xffffffffu, send, m);
                if (hi) v[j] = recv; else v[jp] = recv;
            }
        }
    }
}

// Angle coefficients for group K (stages 3K..3K+2), pair base = blk*4D + off.
template<int K>
__device__ __forceinline__ void load_cs(const float* __restrict__ ang, int t,
                                        float2 cs[3][4]) {
    const int D      = 1 << (3 * K);
    const int base_p = (t >> (3 * K)) * 4 * D + (t & (D - 1));
    if (K == 0) {
#pragma unroll
        for (int u = 0; u < 3; u++) {
            float4 a = __ldg(reinterpret_cast<const float4*>(ang + u * NPAIRS) + t);
            cs[u][0] = cs_poly(a.x);
            cs[u][1] = cs_poly(a.y);
            cs[u][2] = cs_poly(a.z);
            cs[u][3] = cs_poly(a.w);
        }
    } else {
#pragma unroll
        for (int u = 0; u < 3; u++) {
#pragma unroll
            for (int m = 0; m < 4; m++) {
                cs[u][m] = cs_poly(__ldg(ang + (3 * K + u) * NPAIRS + base_p + m * D));
            }
        }
    }
}

// Groups 2 / 3: smem -> regs -> (smem | global), as before.
template<int K>
__device__ __forceinline__ void do_group(float* sm, float* __restrict__ gy,
                                         const float* __restrict__ ang,
                                         int t, long rowBase) {
    const int D      = 1 << (3 * K);
    const int off    = t & (D - 1);
    const int blk    = t >> (3 * K);
    const int base_n = blk * 8 * D + off;

    float2 cs[3][4];
    load_cs<K>(ang, t, cs);

#pragma unroll
    for (int r = 0; r < RPC; r++) {
        float v[8];
        float* smr = sm + r * NCOLS;
#pragma unroll
        for (int j = 0; j < 8; j++)
            v[j] = smr[swz(base_n + D * j)];

        rot3(cs, v);

        if (K == 3) {
#pragma unroll
            for (int j = 0; j < 8; j++)
                gy[rowBase + (long)r * NCOLS + t + 512 * j] = v[j];
        } else {
#pragma unroll
            for (int j = 0; j < 8; j++)
                smr[swz(base_n + D * j)] = v[j];
        }
    }
}

__global__ void __launch_bounds__(TPB, 2)
butterfly_kernel(const float* __restrict__ x, const float* __restrict__ ang,
                 float* __restrict__ y) {
    extern __shared__ float sm[];   // RPC * NCOLS floats = 64 KB
    int t = threadIdx.x;
    unsigned lane = t & 31;
    long rowBase = (long)blockIdx.x * RPC * NCOLS;

    // ---- fused groups 0 + 1: global -> regs -> shfl transpose -> regs -> smem
    {
        float2 cs0[3][4], cs1[3][4];
        load_cs<0>(ang, t, cs0);
        load_cs<1>(ang, t, cs1);

        const int base_n1 = (t >> 3) * 64 + (t & 7);   // group-1 ownership

#pragma unroll
        for (int r = 0; r < RPC; r++) {
            float v[8];
            const float4* p =
                reinterpret_cast<const float4*>(x + rowBase + (long)r * NCOLS + 8 * t);
            float4 f0 = __ldg(p);
            float4 f1 = __ldg(p + 1);
            v[0] = f0.x; v[1] = f0.y; v[2] = f0.z; v[3] = f0.w;
            v[4] = f1.x; v[5] = f1.y; v[6] = f1.z; v[7] = f1.w;

            rot3(cs0, v);                 // stages 0-2 (dist 1,2,4)
            transpose8(v, lane);          // register exchange, no smem
            rot3(cs1, v);                 // stages 3-5 (dist 8,16,32)

            float* smr = sm + r * NCOLS;
#pragma unroll
            for (int j = 0; j < 8; j++)
                smr[swz(base_n1 + 8 * j)] = v[j];
        }
    }
    __syncthreads();
    do_group<2>(sm, y, ang, t, rowBase);   // stages 6-8, smem -> smem
    __syncthreads();
    do_group<3>(sm, y, ang, t, rowBase);   // stages 9-11, smem -> global
}

extern "C" void kernel_launch(void* const* d_in, const int* in_sizes, int n_in,
                              void* d_out, int out_size) {
    const float* x   = (const float*)d_in[0];
    const float* ang = (const float*)d_in[1];
    float* y         = (float*)d_out;

    (void)in_sizes; (void)n_in; (void)out_size;

    cudaFuncSetAttribute(butterfly_kernel,
                         cudaFuncAttributeMaxDynamicSharedMemorySize,
                         RPC * NCOLS * (int)sizeof(float));

    butterfly_kernel<<<NROWS / RPC, TPB, RPC * NCOLS * sizeof(float)>>>(x, ang, y);
}

// round 6
// speedup vs baseline: 1.5137x; 1.5137x over previous
#include <cuda_runtime.h>

#define NSTAGES 12
#define NPAIRS  2048
#define NCOLS   4096
#define NROWS   4096
#define RPC     4       // rows per CTA -> 64 KB smem -> 2 CTAs/SM
#define TPB     512

// Bank-conflict-free swizzle for the smem exchange patterns (D = 8, 64, 512).
__device__ __forceinline__ int swz(int a) {
    return a ^ ((a >> 5) & 7) ^ (((a >> 6) & 3) << 3);
}

// Polynomial sin/cos for |a| <~ 0.15 (angles are 0.02*N(0,1)).
// Returns c1 = cos(a)-1 (no cancellation) and s = sin(a). All FMA-pipe.
__device__ __forceinline__ float2 cs_poly(float a) {
    float x2 = a * a;
    float c1 = x2 * fmaf(x2, (1.0f / 24.0f), -0.5f);
    float s  = a * fmaf(x2, fmaf(x2, (1.0f / 120.0f), (-1.0f / 6.0f)), 1.0f);
    return make_float2(c1, s);
}

// Rotation using c1 = c-1: 4 FFMA, = (c*v0 - s*v1, s*v0 + c*v1).
__device__ __forceinline__ void rot(float2 cs, float& a, float& b) {
    float ta = fmaf(cs.x, a, a);
    float tb = fmaf(cs.x, b, b);
    float y0 = fmaf(-cs.y, b, ta);
    float y1 = fmaf(cs.y, a, tb);
    a = y0;
    b = y1;
}

// Rotation from a raw angle: poly inline (6 FMA) + 4 FMA. Keeps only the
// angle (1 reg) live instead of (c1,s) (2 regs) -> halves angle registers.
__device__ __forceinline__ void rot_a(float th, float& a, float& b) {
    rot(cs_poly(th), a, b);
}

// Three butterfly stages (dist D,2D,4D) on 8 register values, raw angles.
__device__ __forceinline__ void rot3_a(const float th[12], float v[8]) {
#pragma unroll
    for (int m = 0; m < 4; m++) rot_a(th[m], v[2 * m], v[2 * m + 1]);
#pragma unroll
    for (int m = 0; m < 4; m++) {
        int j = ((m >> 1) << 2) | (m & 1);
        rot_a(th[4 + m], v[j], v[j + 2]);
    }
#pragma unroll
    for (int m = 0; m < 4; m++) rot_a(th[8 + m], v[m], v[m + 4]);
}

// Three butterfly stages with precomputed (c1,s) (used in groups 2/3).
__device__ __forceinline__ void rot3(const float2 cs[3][4], float v[8]) {
#pragma unroll
    for (int m = 0; m < 4; m++) rot(cs[0][m], v[2 * m], v[2 * m + 1]);
#pragma unroll
    for (int m = 0; m < 4; m++) {
        int j = ((m >> 1) << 2) | (m & 1);
        rot(cs[1][m], v[j], v[j + 2]);
    }
#pragma unroll
    for (int m = 0; m < 4; m++) rot(cs[2][m], v[m], v[m + 4]);
}

// 8x8 register transpose within each 8-lane group:
// new v[j] on lane l == old v[l&7] on lane (l&24)|j.
__device__ __forceinline__ void transpose8(float v[8], unsigned l) {
#pragma unroll
    for (int m = 1; m <= 4; m <<= 1) {
        bool hi = (l & m) != 0;
#pragma unroll
        for (int j = 0; j < 8; j++) {
            if ((j & m) == 0) {
                int jp = j | m;
                float send = hi ? v[j] : v[jp];
                float recv = __shfl_xor_sync(0xffffffffu, send, m);
                if (hi) v[j] = recv; else v[jp] = recv;
            }
        }
    }
}

// Precomputed (c1,s) for group K (stages 3K..3K+2), pair base = blk*4D + off.
template<int K>
__device__ __forceinline__ void load_cs(const float* __restrict__ ang, int t,
                                        float2 cs[3][4]) {
    const int D      = 1 << (3 * K);
    const int base_p = (t >> (3 * K)) * 4 * D + (t & (D - 1));
#pragma unroll
    for (int u = 0; u < 3; u++) {
#pragma unroll
        for (int m = 0; m < 4; m++) {
            cs[u][m] = cs_poly(__ldg(ang + (3 * K + u) * NPAIRS + base_p + m * D));
        }
    }
}

// Groups 2 / 3: smem -> regs -> (smem | global). Proven R4 path.
template<int K>
__device__ __forceinline__ void do_group(float* sm, float* __restrict__ gy,
                                         const float* __restrict__ ang,
                                         int t, long rowBase) {
    const int D      = 1 << (3 * K);
    const int off    = t & (D - 1);
    const int blk    = t >> (3 * K);
    const int base_n = blk * 8 * D + off;

    float2 cs[3][4];
    load_cs<K>(ang, t, cs);

#pragma unroll
    for (int r = 0; r < RPC; r++) {
        float v[8];
        float* smr = sm + r * NCOLS;
#pragma unroll
        for (int j = 0; j < 8; j++)
            v[j] = smr[swz(base_n + D * j)];

        rot3(cs, v);

        if (K == 3) {
#pragma unroll
            for (int j = 0; j < 8; j++)
                gy[rowBase + (long)r * NCOLS + t + 512 * j] = v[j];
        } else {
#pragma unroll
            for (int j = 0; j < 8; j++)
                smr[swz(base_n + D * j)] = v[j];
        }
    }
}

__global__ void __launch_bounds__(TPB, 2)
butterfly_kernel(const float* __restrict__ x, const float* __restrict__ ang,
                 float* __restrict__ y) {
    extern __shared__ float sm[];   // RPC * NCOLS floats = 64 KB
    int t = threadIdx.x;
    unsigned lane = t & 31;
    long rowBase = (long)blockIdx.x * RPC * NCOLS;

    // ---- fused groups 0 + 1: global -> regs -> shfl transpose -> regs -> smem
    // Raw angles only (24 regs); poly computed inline per rotation.
    {
        float th0[12], th1[12];
        // group 0: base_p = 4t -> contiguous, 3x float4
#pragma unroll
        for (int u = 0; u < 3; u++) {
            float4 a = __ldg(reinterpret_cast<const float4*>(ang + u * NPAIRS) + t);
            th0[u * 4 + 0] = a.x;
            th0[u * 4 + 1] = a.y;
            th0[u * 4 + 2] = a.z;
            th0[u * 4 + 3] = a.w;
        }
        // group 1: D=8, base_p = (t>>3)*32 + (t&7)
        {
            const int base_p1 = (t >> 3) * 32 + (t & 7);
#pragma unroll
            for (int u = 0; u < 3; u++)
#pragma unroll
                for (int m = 0; m < 4; m++)
                    th1[u * 4 + m] = __ldg(ang + (3 + u) * NPAIRS + base_p1 + m * 8);
        }

        const int base_n1 = (t >> 3) * 64 + (t & 7);   // group-1 ownership

#pragma unroll
        for (int r = 0; r < RPC; r++) {
            float v[8];
            const float4* p =
                reinterpret_cast<const float4*>(x + rowBase + (long)r * NCOLS + 8 * t);
            float4 f0 = __ldg(p);
            float4 f1 = __ldg(p + 1);
            v[0] = f0.x; v[1] = f0.y; v[2] = f0.z; v[3] = f0.w;
            v[4] = f1.x; v[5] = f1.y; v[6] = f1.z; v[7] = f1.w;

            rot3_a(th0, v);               // stages 0-2 (dist 1,2,4)
            transpose8(v, lane);          // register exchange, no smem
            rot3_a(th1, v);               // stages 3-5 (dist 8,16,32)

            float* smr = sm + r * NCOLS;
#pragma unroll
            for (int j = 0; j < 8; j++)
                smr[swz(base_n1 + 8 * j)] = v[j];
        }
    }
    __syncthreads();
    do_group<2>(sm, y, ang, t, rowBase);   // stages 6-8, smem -> smem
    __syncthreads();
    do_group<3>(sm, y, ang, t, rowBase);   // stages 9-11, smem -> global
}

extern "C" void kernel_launch(void* const* d_in, const int* in_sizes, int n_in,
                              void* d_out, int out_size) {
    const float* x   = (const float*)d_in[0];
    const float* ang = (const float*)d_in[1];
    float* y         = (float*)d_out;

    (void)in_sizes; (void)n_in; (void)out_size;

    cudaFuncSetAttribute(butterfly_kernel,
                         cudaFuncAttributeMaxDynamicSharedMemorySize,
                         RPC * NCOLS * (int)sizeof(float));

    butterfly_kernel<<<NROWS / RPC, TPB, RPC * NCOLS * sizeof(float)>>>(x, ang, y);
}